// round 16
// baseline (speedup 1.0000x reference)
#include <cuda_runtime.h>
#include <cuda.h>
#include <cuda_fp16.h>
#include <math.h>
#include <stdint.h>

#define BB 4
#define SS 4096
#define DD 1024
#define KK 8
#define RC 256
#define MIDD 256

// ---------------- scratch (device globals; no allocs allowed) ----------------
__device__ float g_RBs[16 * MIDD];
__device__ float g_CBs[16 * MIDD];
__device__ float g_Ms[16 * 16];
__device__ float g_CB2[16 * DD];
__device__ float g_U[BB * SS * 16];
__device__ float g_V[BB * SS * 16];
__device__ float g_Lr[BB * SS];
__device__ float g_Part[(size_t)BB * SS * 64];
__device__ __half g_Ph[(size_t)BB * SS * SS];
__device__ __half g_Xh[(size_t)BB * SS * DD];
__device__ __half g_Hh[(size_t)BB * SS * DD];
__device__ __half g_Wh[DD * DD];

// ---------------- helpers ----------------
__device__ __forceinline__ float fexp2(float x) {
    x = fmaxf(x, -60.0f);
    float fl = floorf(x);
    float f = x - fl;
    float p = 1.5403530393e-4f;
    p = fmaf(p, f, 1.3333558146e-3f);
    p = fmaf(p, f, 9.6181291076e-3f);
    p = fmaf(p, f, 5.5504108664e-2f);
    p = fmaf(p, f, 2.4022650696e-1f);
    p = fmaf(p, f, 6.9314718056e-1f);
    p = fmaf(p, f, 1.0f);
    int e = (int)fl;
    return p * __int_as_float((e + 127) << 23);
}
__device__ __forceinline__ float gelu_exact(float v) {
    return 0.5f * v * (1.0f + erff(v * 0.70710678118654752f));
}
__device__ __forceinline__ uint32_t s2u(const void* p) {
    uint32_t a;
    asm("{ .reg .u64 t; cvta.to.shared.u64 t, %1; cvt.u32.u64 %0, t; }" : "=r"(a) : "l"(p));
    return a;
}
__device__ __forceinline__ void cpa16(uint32_t dst, const void* src) {
    asm volatile("cp.async.cg.shared.global [%0], [%1], 16;" :: "r"(dst), "l"(src));
}
#define CPA_COMMIT() asm volatile("cp.async.commit_group;" ::: "memory")

__device__ __forceinline__ void mma_f16(float* c, const uint32_t* a, const uint32_t* b) {
    asm volatile(
        "mma.sync.aligned.m16n8k16.row.col.f32.f16.f16.f32 "
        "{%0,%1,%2,%3}, {%4,%5,%6,%7}, {%8,%9}, {%0,%1,%2,%3};"
        : "+f"(c[0]), "+f"(c[1]), "+f"(c[2]), "+f"(c[3])
        : "r"(a[0]), "r"(a[1]), "r"(a[2]), "r"(a[3]), "r"(b[0]), "r"(b[1]));
}
#define LDSM4(r0, r1, r2, r3, addr)                                           \
    asm volatile("ldmatrix.sync.aligned.m8n8.x4.shared.b16 {%0,%1,%2,%3}, [%4];" \
                 : "=r"(r0), "=r"(r1), "=r"(r2), "=r"(r3) : "r"(addr))
#define LDSM4T(r0, r1, r2, r3, addr)                                          \
    asm volatile("ldmatrix.sync.aligned.m8n8.x4.trans.shared.b16 {%0,%1,%2,%3}, [%4];" \
                 : "=r"(r0), "=r"(r1), "=r"(r2), "=r"(r3) : "r"(addr))

// SMEM: k-chunk 64. A tile [128 m][64 k] pad 72 halfs. B ctx [64 k][128 n] pad 136; B out [128 n][64 k] pad 72.
#define APAD2 72
#define BPADT 136
#define ABUF2 9216
#define BBUF2 9216
#define BUF2 (ABUF2 + BBUF2)
#define NSTAGE 3
#define GSMEM (NSTAGE * BUF2 * 2)   // 110592 bytes

// ---------------- stage 1: basis reductions ----------------
__global__ void k_rbs(const float* __restrict__ rb) {
    int r = blockIdx.x, m = threadIdx.x;
    const float* src = rb + (size_t)r * DD * MIDD + m;
    float s = 0.f;
#pragma unroll 8
    for (int d = 0; d < DD; ++d) s += src[(size_t)d * MIDD];
    g_RBs[r * MIDD + m] = s;
}
__global__ void k_cbs(const float* __restrict__ cb) {
    int gw = (blockIdx.x * blockDim.x + threadIdx.x) >> 5;
    int lane = threadIdx.x & 31;
    int c = gw >> 8, m = gw & 255;
    const float* src = cb + (size_t)c * MIDD * DD + (size_t)m * DD;
    float s = 0.f;
    for (int d = lane; d < DD; d += 32) s += src[d];
#pragma unroll
    for (int o = 16; o; o >>= 1) s += __shfl_xor_sync(0xffffffffu, s, o);
    if (lane == 0) g_CBs[c * MIDD + m] = s;
}
__global__ void k_cb2(const float* __restrict__ cb) {
    int idx = blockIdx.x * blockDim.x + threadIdx.x;
    int c = idx >> 10, d = idx & 1023;
    const float* src = cb + (size_t)c * MIDD * DD + d;
    float s = 0.f;
#pragma unroll 8
    for (int m = 0; m < MIDD; ++m) s += src[(size_t)m * DD];
    g_CB2[c * DD + d] = s;
}
__global__ void k_M() {
    int r = blockIdx.x, c = blockIdx.y, lane = threadIdx.x;
    const float* a = g_RBs + r * MIDD;
    const float* bb = g_CBs + c * MIDD;
    float s = 0.f;
#pragma unroll
    for (int i = 0; i < 8; ++i) s = fmaf(a[lane + 32 * i], bb[lane + 32 * i], s);
#pragma unroll
    for (int o = 16; o; o >>= 1) s += __shfl_xor_sync(0xffffffffu, s, o);
    if (lane == 0) g_Ms[r * 16 + c] = s * (1.4426950408889634f / 16.0f);
}

// ---------------- stage 2: routing -> U, V ----------------
__global__ void k_route(const int* __restrict__ nidx, const float* __restrict__ nw,
                        const float* __restrict__ nrec) {
    int n = (blockIdx.x * blockDim.x + threadIdx.x) >> 5;
    int lane = threadIdx.x & 31;
    float acc[8];
#pragma unroll
    for (int j = 0; j < 8; ++j) acc[j] = 0.f;
#pragma unroll
    for (int k = 0; k < KK; ++k) {
        int id = __ldg(&nidx[n * KK + k]);
        float w = __ldg(&nw[n * KK + k]);
        const float* base = nrec + (size_t)id * RC;
        float e[8];
        float s = 0.f;
#pragma unroll
        for (int j = 0; j < 8; ++j) {
            float v = __expf(base[lane + 32 * j]);
            e[j] = v; s += v;
        }
#pragma unroll
        for (int o = 16; o; o >>= 1) s += __shfl_xor_sync(0xffffffffu, s, o);
        float ws = w / s;
#pragma unroll
        for (int j = 0; j < 8; ++j) acc[j] = fmaf(e[j], ws, acc[j]);
    }
    float e2[8];
    float s2 = 0.f;
#pragma unroll
    for (int j = 0; j < 8; ++j) { float v = __expf(acc[j]); e2[j] = v; s2 += v; }
#pragma unroll
    for (int o = 16; o; o >>= 1) s2 += __shfl_xor_sync(0xffffffffu, s2, o);
    float inv2 = 1.0f / s2;
    float tsum = 0.f;
#pragma unroll
    for (int j = 0; j < 8; ++j) tsum += e2[j];
    tsum *= inv2;
    float cs = tsum + __shfl_xor_sync(0xffffffffu, tsum, 16);
    float rs[8];
#pragma unroll
    for (int j = 0; j < 8; ++j) {
        float v = e2[j] * inv2;
        v += __shfl_xor_sync(0xffffffffu, v, 1);
        v += __shfl_xor_sync(0xffffffffu, v, 2);
        v += __shfl_xor_sync(0xffffffffu, v, 4);
        v += __shfl_xor_sync(0xffffffffu, v, 8);
        rs[j] = v;
    }
    float u = 0.f;
#pragma unroll
    for (int r = 0; r < 16; ++r) {
        float rw = __shfl_sync(0xffffffffu, rs[r >> 1], (r & 1) << 4);
        if (lane < 16) u = fmaf(rw, g_Ms[r * 16 + lane], u);
    }
    if (lane < 16) {
        g_U[(size_t)n * 16 + lane] = u;
        g_V[(size_t)n * 16 + lane] = cs;
    }
}

// ---------------- stage 3: tile-parallel P = exp2(U·V) -> fp16 + partial rowsums ----------------
__global__ void k_smax2() {
    int kt = blockIdx.x, qt = blockIdx.y, b = blockIdx.z;
    bool pad = (kt == qt + 1) && ((qt & 1) == 0);
    if (kt > qt && !pad) return;
    int tid = threadIdx.x;
    int row = tid >> 2, sub = tid & 3;
    int wid = tid >> 5, lane = tid & 31;
    __half* gp = g_Ph + ((size_t)b * SS + (size_t)qt * 64) * SS + (size_t)kt * 64;
    if (pad) {
        __half2 z = __floats2half2_rn(0.f, 0.f);
#pragma unroll
        for (int r = 0; r < 8; ++r)
            *(__half2*)(gp + (size_t)(wid * 8 + r) * SS + 2 * lane) = z;
        return;
    }
    __shared__ float Us[64 * 20];
    __shared__ float Vs[64 * 20];
    __shared__ float Ps[64 * 66];
    {
        int vr = tid >> 2, c4 = (tid & 3) * 4;
        *(float4*)(Us + vr * 20 + c4) =
            *(const float4*)(g_U + ((size_t)b * SS + (size_t)qt * 64 + vr) * 16 + c4);
        *(float4*)(Vs + vr * 20 + c4) =
            *(const float4*)(g_V + ((size_t)b * SS + (size_t)kt * 64 + vr) * 16 + c4);
    }
    __syncthreads();
    float ur[16];
#pragma unroll
    for (int i = 0; i < 16; ++i) ur[i] = Us[row * 20 + i];
    float psum = 0.f;
    bool diag = (kt == qt);
#pragma unroll
    for (int j = 0; j < 16; ++j) {
        int key = sub + 4 * j;
        const float* vv = Vs + key * 20;
        float s = 0.f;
#pragma unroll
        for (int i = 0; i < 16; ++i) s = fmaf(ur[i], vv[i], s);
        float p = (diag && key > row) ? 0.f : fexp2(s);
        Ps[row * 66 + key] = p;
        psum += p;
    }
    psum += __shfl_xor_sync(0xffffffffu, psum, 1);
    psum += __shfl_xor_sync(0xffffffffu, psum, 2);
    if (sub == 0)
        g_Part[((size_t)b * SS + (size_t)qt * 64 + row) * 64 + kt] = psum;
    __syncthreads();
#pragma unroll
    for (int r = 0; r < 8; ++r) {
        int rr = wid * 8 + r;
        float2 v2 = *(float2*)(Ps + rr * 66 + 2 * lane);
        *(__half2*)(gp + (size_t)rr * SS + 2 * lane) = __floats2half2_rn(v2.x, v2.y);
    }
}
__global__ void k_lr() {
    int row = blockIdx.x * 8 + (threadIdx.x >> 5);
    int lane = threadIdx.x & 31;
    int qt = (row & (SS - 1)) >> 6;
    const float* part = g_Part + (size_t)row * 64;
    float s = 0.f;
    if (lane <= qt) s = part[lane];
    if (lane + 32 <= qt) s += part[lane + 32];
#pragma unroll
    for (int o = 16; o; o >>= 1) s += __shfl_xor_sync(0xffffffffu, s, o);
    if (lane == 0) g_Lr[row] = 1.0f / s;
}

// ---------------- stage 3b: x -> fp16 (coalesced); W -> fp16 ----------------
__global__ void k_xh(const float* __restrict__ x) {
    size_t i = ((size_t)blockIdx.x * blockDim.x + threadIdx.x) * 8;
    float4 a = *(const float4*)(x + i);
    float4 b = *(const float4*)(x + i + 4);
    __half2 h[4];
    h[0] = __floats2half2_rn(a.x, a.y);
    h[1] = __floats2half2_rn(a.z, a.w);
    h[2] = __floats2half2_rn(b.x, b.y);
    h[3] = __floats2half2_rn(b.z, b.w);
    *(uint4*)(g_Xh + i) = *(uint4*)h;
}
__global__ void k_wh(const float* __restrict__ w) {
    int i = blockIdx.x * blockDim.x + threadIdx.x;
    g_Wh[i] = __float2half_rn(w[i]);
}

// ---------------- fp16 mma GEMM core: CTA 128x128, 2x4 warps (warp 64x32) ----------------
// 3-stage cp.async ring, k-chunk 64, ldmatrix fragment loads, fragment double-buffering.
struct Frag {
    uint32_t a[4][4];
    uint32_t b[4][2];
};

template <bool BT>
__device__ __forceinline__ void load_frag(Frag& f, uint32_t Au, uint32_t Bu, int ks) {
#pragma unroll
    for (int m2 = 0; m2 < 4; ++m2)
        LDSM4(f.a[m2][0], f.a[m2][1], f.a[m2][2], f.a[m2][3],
              Au + (m2 * 16 * APAD2 + ks * 16) * 2);
#pragma unroll
    for (int nb = 0; nb < 2; ++nb) {
        if (BT)
            LDSM4T(f.b[2 * nb][0], f.b[2 * nb][1], f.b[2 * nb + 1][0], f.b[2 * nb + 1][1],
                   Bu + (ks * 16 * BPADT + nb * 16) * 2);
        else
            LDSM4(f.b[2 * nb][0], f.b[2 * nb][1], f.b[2 * nb + 1][0], f.b[2 * nb + 1][1],
                  Bu + (nb * 16 * APAD2 + ks * 16) * 2);
    }
}

__device__ __forceinline__ void load_tileA(uint32_t au, const __half* Ag, int ldA, int k0, int tid) {
#pragma unroll
    for (int i = 0; i < 4; ++i) {
        int idx = tid + i * 256;
        int row = idx >> 3, seg = idx & 7;
        cpa16(au + (row * APAD2 + seg * 8) * 2, Ag + (size_t)row * ldA + k0 + seg * 8);
    }
}
template <bool BT>
__device__ __forceinline__ void load_tileB(uint32_t bu, const __half* Bg, int ldB, int k0, int tid) {
    if (BT) {
#pragma unroll
        for (int i = 0; i < 4; ++i) {
            int idx = tid + i * 256;
            int row = idx >> 4, seg = idx & 15;
            cpa16(bu + (row * BPADT + seg * 8) * 2, Bg + (size_t)(k0 + row) * ldB + seg * 8);
        }
    } else {
#pragma unroll
        for (int i = 0; i < 4; ++i) {
            int idx = tid + i * 256;
            int row = idx >> 3, seg = idx & 7;
            cpa16(bu + (row * APAD2 + seg * 8) * 2, Bg + (size_t)row * ldB + k0 + seg * 8);
        }
    }
}

template <bool BT>
__device__ __forceinline__ void gemm_f16(float* smf,
                                         const __half* Ag, int ldA,
                                         const __half* Bg, int ldB,
                                         int nch, float acc[4][4][4], int tid) {
    __half* sm = (__half*)smf;
    int wid = tid >> 5, lane = tid & 31;
    int wm = wid & 1, wn = wid >> 1;
    uint32_t smu = s2u(sm);

    uint32_t a_off = ((wm * 64 + (lane & 7) + ((lane >> 3) & 1) * 8) * APAD2 + (lane >> 4) * 8) * 2;
    uint32_t b_off;
    if (BT) b_off = (((lane & 7) + ((lane >> 3) & 1) * 8) * BPADT + wn * 32 + (lane >> 4) * 8) * 2;
    else    b_off = ((wn * 32 + (lane & 7) + (lane >> 4) * 8) * APAD2 + ((lane >> 3) & 1) * 8) * 2;

#pragma unroll
    for (int s = 0; s < NSTAGE - 1; ++s) {
        uint32_t bu = smu + s * BUF2 * 2;
        load_tileA(bu, Ag, ldA, s * 64, tid);
        load_tileB<BT>(bu + ABUF2 * 2, Bg, ldB, s * 64, tid);
        CPA_COMMIT();
    }
    int stg = 0;
    for (int c = 0; c < nch; ++c) {
        asm volatile("cp.async.wait_group %0;" :: "n"(NSTAGE - 2) : "memory");
        __syncthreads();
        if (c + NSTAGE - 1 < nch) {
            int s = stg + NSTAGE - 1;
            if (s >= NSTAGE) s -= NSTAGE;
            uint32_t bu = smu + s * BUF2 * 2;
            load_tileA(bu, Ag, ldA, (c + NSTAGE - 1) * 64, tid);
            load_tileB<BT>(bu + ABUF2 * 2, Bg, ldB, (c + NSTAGE - 1) * 64, tid);
        }
        CPA_COMMIT();
        uint32_t bufu = smu + stg * BUF2 * 2;
        if (++stg == NSTAGE) stg = 0;
        uint32_t Au = bufu + a_off;
        uint32_t Bu = bufu + ABUF2 * 2 + b_off;

        Frag f[2];
        load_frag<BT>(f[0], Au, Bu, 0);
#pragma unroll
        for (int ks = 0; ks < 4; ++ks) {
            if (ks < 3) load_frag<BT>(f[(ks + 1) & 1], Au, Bu, ks + 1);
            const Frag& fc = f[ks & 1];
#pragma unroll
            for (int m2 = 0; m2 < 4; ++m2)
#pragma unroll
                for (int n2 = 0; n2 < 4; ++n2)
                    mma_f16(acc[m2][n2], fc.a[m2], fc.b[n2]);
        }
    }
    __syncthreads();
}

// ---------------- stage 4: context GEMM + fused epilogue -> g_Hh ----------------
// grid (x = nt FASTEST for P L2 reuse, y = mt big-first, z = b)
__global__ void __launch_bounds__(256, 2) k_ctx_mma(const float* __restrict__ alphap) {
    extern __shared__ __align__(16) float sm[];
    int nt = blockIdx.x;
    int mt = (gridDim.y - 1) - blockIdx.y;
    int b = blockIdx.z;
    int tid = threadIdx.x;
    int wid = tid >> 5, lane = tid & 31;
    int g = lane >> 2, t = lane & 3;
    int wm = wid & 1, wn = wid >> 1;

    const __half* Ag = g_Ph + ((size_t)b * SS + (size_t)mt * 128) * SS;
    const __half* Bg = g_Xh + (size_t)b * SS * DD + nt * 128;
    int nch = (mt + 1) * 2;

    float acc[4][4][4];
#pragma unroll
    for (int i = 0; i < 4; ++i)
#pragma unroll
        for (int j = 0; j < 4; ++j)
#pragma unroll
            for (int k = 0; k < 4; ++k) acc[i][j][k] = 0.f;

    gemm_f16<true>(sm, Ag, SS, Bg, DD, nch, acc, tid);

    // epilogue staging
    float* Vq = sm;           // [128][16]
    float* lrs = sm + 2048;   // [128]
    float* c2 = sm + 2176;    // [16][128]
    for (int i = tid; i < 2048; i += 256)
        Vq[i] = g_V[((size_t)b * SS + (size_t)mt * 128) * 16 + i];
    if (tid < 128) lrs[tid] = g_Lr[(size_t)b * SS + mt * 128 + tid];
    for (int i = tid; i < 2048; i += 256) {
        int cc = i >> 7, d = i & 127;
        c2[i] = g_CB2[cc * DD + nt * 128 + d];
    }
    __syncthreads();

    float alpha = __ldg(alphap);
#pragma unroll
    for (int m2 = 0; m2 < 4; ++m2) {
#pragma unroll
        for (int rr = 0; rr < 2; ++rr) {
            int row = wm * 64 + m2 * 16 + g + rr * 8;
            float lr = lrs[row];
            const float* vr = Vq + row * 16;
            __half* hrow = g_Hh + ((size_t)b * SS + (size_t)mt * 128 + row) * DD + nt * 128;
#pragma unroll
            for (int n2 = 0; n2 < 4; ++n2) {
                int col = wn * 32 + n2 * 8 + 2 * t;
                float tr0 = 0.f, tr1 = 0.f;
#pragma unroll
                for (int cc = 0; cc < 16; ++cc) {
                    float vv = vr[cc];
                    tr0 = fmaf(vv, c2[cc * 128 + col], tr0);
                    tr1 = fmaf(vv, c2[cc * 128 + col + 1], tr1);
                }
                float z0 = fmaf(acc[m2][n2][rr * 2 + 0], lr, alpha * tr0);
                float z1 = fmaf(acc[m2][n2][rr * 2 + 1], lr, alpha * tr1);
                z0 = gelu_exact(z0);
                z1 = gelu_exact(z1);
                *(__half2*)(hrow + col) = __floats2half2_rn(z0, z1);
            }
        }
    }
}

// ---------------- stage 5: out = H @ W^T + b ----------------
// grid (x = nt FASTEST for H L2 reuse, y = mt)
__global__ void __launch_bounds__(256, 2) k_out_mma(const float* __restrict__ ob,
                                                    float* __restrict__ out) {
    extern __shared__ __align__(16) float sm[];
    int nt = blockIdx.x;
    int mt = blockIdx.y;
    int tid = threadIdx.x;
    int wid = tid >> 5, lane = tid & 31;
    int g = lane >> 2, t = lane & 3;
    int wm = wid & 1, wn = wid >> 1;

    const __half* Ag = g_Hh + (size_t)mt * 128 * DD;
    const __half* Bg = g_Wh + (size_t)nt * 128 * DD;

    float acc[4][4][4];
#pragma unroll
    for (int i = 0; i < 4; ++i)
#pragma unroll
        for (int j = 0; j < 4; ++j)
#pragma unroll
            for (int k = 0; k < 4; ++k) acc[i][j][k] = 0.f;

    gemm_f16<false>(sm, Ag, DD, Bg, DD, 16, acc, tid);

    float* bs = sm;
    if (tid < 32) *(float4*)(bs + tid * 4) = *(const float4*)(ob + nt * 128 + tid * 4);
    __syncthreads();

#pragma unroll
    for (int m2 = 0; m2 < 4; ++m2) {
#pragma unroll
        for (int rr = 0; rr < 2; ++rr) {
            int row = wm * 64 + m2 * 16 + g + rr * 8;
            float* orow = out + ((size_t)mt * 128 + row) * DD + nt * 128;
#pragma unroll
            for (int n2 = 0; n2 < 4; ++n2) {
                int col = wn * 32 + n2 * 8 + 2 * t;
                float z0 = acc[m2][n2][rr * 2 + 0] + bs[col];
                float z1 = acc[m2][n2][rr * 2 + 1] + bs[col + 1];
                *(float2*)(orow + col) = make_float2(z0, z1);
            }
        }
    }
}

// ---------------- launcher ----------------
extern "C" void kernel_launch(void* const* d_in, const int* in_sizes, int n_in,
                              void* d_out, int out_size) {
    const float* x    = (const float*)d_in[0];
    const int*   nidx = (const int*)d_in[1];
    const float* nw   = (const float*)d_in[2];
    const float* nrec = (const float*)d_in[3];
    const float* rb   = (const float*)d_in[4];
    const float* cb   = (const float*)d_in[5];
    const float* ow   = (const float*)d_in[6];
    const float* ob   = (const float*)d_in[7];
    const float* alp  = (const float*)d_in[8];
    float* out = (float*)d_out;

    cudaFuncSetAttribute(k_ctx_mma, cudaFuncAttributeMaxDynamicSharedMemorySize, GSMEM);
    cudaFuncSetAttribute(k_out_mma, cudaFuncAttributeMaxDynamicSharedMemorySize, GSMEM);

    k_rbs<<<16, 256>>>(rb);
    k_cbs<<<512, 256>>>(cb);
    k_cb2<<<64, 256>>>(cb);
    k_M<<<dim3(16, 16), 32>>>();
    k_route<<<(BB * SS * 32) / 256, 256>>>(nidx, nw, nrec);
    k_smax2<<<dim3(64, 64, BB), 256>>>();
    k_lr<<<BB * SS / 8, 256>>>();
    k_xh<<<(BB * SS * DD) / (256 * 8), 256>>>(x);
    k_wh<<<DD * DD / 256, 256>>>(ow);
    k_ctx_mma<<<dim3(8, 32, BB), 256, GSMEM>>>(alp);
    k_out_mma<<<dim3(8, BB * SS / 128), 256, GSMEM>>>(ob, out);
}

// round 17
// speedup vs baseline: 1.1650x; 1.1650x over previous
#include <cuda_runtime.h>
#include <cuda.h>
#include <cuda_fp16.h>
#include <math.h>
#include <stdint.h>

#define BB 4
#define SS 4096
#define DD 1024
#define KK 8
#define RC 256
#define MIDD 256

// ---------------- scratch (device globals; no allocs allowed) ----------------
__device__ float g_RBs[16 * MIDD];
__device__ float g_RBsPart[16 * 8 * MIDD];
__device__ float g_CBs[16 * MIDD];
__device__ float g_Ms[16 * 16];
__device__ float g_CB2[16 * DD];
__device__ float g_U[BB * SS * 16];
__device__ float g_V[BB * SS * 16];
__device__ float g_Lr[BB * SS];
__device__ float g_Part[(size_t)BB * SS * 64];
__device__ __half g_Ph[(size_t)BB * SS * SS];
__device__ __half g_Xh[(size_t)BB * SS * DD];
__device__ __half g_Hh[(size_t)BB * SS * DD];
__device__ __half g_Wh[DD * DD];

// ---------------- helpers ----------------
__device__ __forceinline__ float fexp2(float x) {
    x = fmaxf(x, -60.0f);
    float fl = floorf(x);
    float f = x - fl;
    float p = 1.5403530393e-4f;
    p = fmaf(p, f, 1.3333558146e-3f);
    p = fmaf(p, f, 9.6181291076e-3f);
    p = fmaf(p, f, 5.5504108664e-2f);
    p = fmaf(p, f, 2.4022650696e-1f);
    p = fmaf(p, f, 6.9314718056e-1f);
    p = fmaf(p, f, 1.0f);
    int e = (int)fl;
    return p * __int_as_float((e + 127) << 23);
}
__device__ __forceinline__ float gelu_exact(float v) {
    return 0.5f * v * (1.0f + erff(v * 0.70710678118654752f));
}
__device__ __forceinline__ uint32_t s2u(const void* p) {
    uint32_t a;
    asm("{ .reg .u64 t; cvta.to.shared.u64 t, %1; cvt.u32.u64 %0, t; }" : "=r"(a) : "l"(p));
    return a;
}
__device__ __forceinline__ void cpa16(uint32_t dst, const void* src) {
    asm volatile("cp.async.cg.shared.global [%0], [%1], 16;" :: "r"(dst), "l"(src));
}
#define CPA_COMMIT() asm volatile("cp.async.commit_group;" ::: "memory")

__device__ __forceinline__ void mma_f16(float* c, const uint32_t* a, const uint32_t* b) {
    asm volatile(
        "mma.sync.aligned.m16n8k16.row.col.f32.f16.f16.f32 "
        "{%0,%1,%2,%3}, {%4,%5,%6,%7}, {%8,%9}, {%0,%1,%2,%3};"
        : "+f"(c[0]), "+f"(c[1]), "+f"(c[2]), "+f"(c[3])
        : "r"(a[0]), "r"(a[1]), "r"(a[2]), "r"(a[3]), "r"(b[0]), "r"(b[1]));
}
#define LDSM4(r0, r1, r2, r3, addr)                                           \
    asm volatile("ldmatrix.sync.aligned.m8n8.x4.shared.b16 {%0,%1,%2,%3}, [%4];" \
                 : "=r"(r0), "=r"(r1), "=r"(r2), "=r"(r3) : "r"(addr))
#define LDSM4T(r0, r1, r2, r3, addr)                                          \
    asm volatile("ldmatrix.sync.aligned.m8n8.x4.trans.shared.b16 {%0,%1,%2,%3}, [%4];" \
                 : "=r"(r0), "=r"(r1), "=r"(r2), "=r"(r3) : "r"(addr))

// SMEM: k-chunk 64. A tile [128 m][64 k] pad 72 halfs. B ctx [64 k][128 n] pad 136; B out [128 n][64 k] pad 72.
#define APAD2 72
#define BPADT 136
#define ABUF2 9216
#define BBUF2 9216
#define BUF2 (ABUF2 + BBUF2)
#define NSTAGE 3
#define GSMEM (NSTAGE * BUF2 * 2)   // 110592 bytes

// ---------------- stage 1: basis reductions ----------------
// two-phase rbs: 128 CTAs of coalesced partial sums, then fold 8 partials
__global__ void k_rbs1(const float* __restrict__ rb) {
    int r = blockIdx.x, dc = blockIdx.y, m = threadIdx.x;
    const float* src = rb + (size_t)r * DD * MIDD + (size_t)dc * 128 * MIDD + m;
    float s = 0.f;
#pragma unroll 8
    for (int d = 0; d < 128; ++d) s += src[(size_t)d * MIDD];
    g_RBsPart[(r * 8 + dc) * MIDD + m] = s;
}
__global__ void k_rbs2() {
    int r = blockIdx.x, m = threadIdx.x;
    const float* part = g_RBsPart + r * 8 * MIDD + m;
    float s = 0.f;
#pragma unroll
    for (int dc = 0; dc < 8; ++dc) s += part[dc * MIDD];
    g_RBs[r * MIDD + m] = s;
}
__global__ void k_cbs(const float* __restrict__ cb) {
    int gw = (blockIdx.x * blockDim.x + threadIdx.x) >> 5;
    int lane = threadIdx.x & 31;
    int c = gw >> 8, m = gw & 255;
    const float* src = cb + (size_t)c * MIDD * DD + (size_t)m * DD;
    float s = 0.f;
    for (int d = lane; d < DD; d += 32) s += src[d];
#pragma unroll
    for (int o = 16; o; o >>= 1) s += __shfl_xor_sync(0xffffffffu, s, o);
    if (lane == 0) g_CBs[c * MIDD + m] = s;
}
__global__ void k_cb2(const float* __restrict__ cb) {
    int idx = blockIdx.x * blockDim.x + threadIdx.x;
    int c = idx >> 10, d = idx & 1023;
    const float* src = cb + (size_t)c * MIDD * DD + d;
    float s = 0.f;
#pragma unroll 8
    for (int m = 0; m < MIDD; ++m) s += src[(size_t)m * DD];
    g_CB2[c * DD + d] = s;
}
__global__ void k_M() {
    int r = blockIdx.x, c = blockIdx.y, lane = threadIdx.x;
    const float* a = g_RBs + r * MIDD;
    const float* bb = g_CBs + c * MIDD;
    float s = 0.f;
#pragma unroll
    for (int i = 0; i < 8; ++i) s = fmaf(a[lane + 32 * i], bb[lane + 32 * i], s);
#pragma unroll
    for (int o = 16; o; o >>= 1) s += __shfl_xor_sync(0xffffffffu, s, o);
    if (lane == 0) g_Ms[r * 16 + c] = s * (1.4426950408889634f / 16.0f);
}

// ---------------- stage 2: routing -> U, V ----------------
__global__ void k_route(const int* __restrict__ nidx, const float* __restrict__ nw,
                        const float* __restrict__ nrec) {
    int n = (blockIdx.x * blockDim.x + threadIdx.x) >> 5;
    int lane = threadIdx.x & 31;
    float acc[8];
#pragma unroll
    for (int j = 0; j < 8; ++j) acc[j] = 0.f;
#pragma unroll
    for (int k = 0; k < KK; ++k) {
        int id = __ldg(&nidx[n * KK + k]);
        float w = __ldg(&nw[n * KK + k]);
        const float* base = nrec + (size_t)id * RC;
        float e[8];
        float s = 0.f;
#pragma unroll
        for (int j = 0; j < 8; ++j) {
            float v = __expf(base[lane + 32 * j]);
            e[j] = v; s += v;
        }
#pragma unroll
        for (int o = 16; o; o >>= 1) s += __shfl_xor_sync(0xffffffffu, s, o);
        float ws = w / s;
#pragma unroll
        for (int j = 0; j < 8; ++j) acc[j] = fmaf(e[j], ws, acc[j]);
    }
    float e2[8];
    float s2 = 0.f;
#pragma unroll
    for (int j = 0; j < 8; ++j) { float v = __expf(acc[j]); e2[j] = v; s2 += v; }
#pragma unroll
    for (int o = 16; o; o >>= 1) s2 += __shfl_xor_sync(0xffffffffu, s2, o);
    float inv2 = 1.0f / s2;
    float tsum = 0.f;
#pragma unroll
    for (int j = 0; j < 8; ++j) tsum += e2[j];
    tsum *= inv2;
    float cs = tsum + __shfl_xor_sync(0xffffffffu, tsum, 16);
    float rs[8];
#pragma unroll
    for (int j = 0; j < 8; ++j) {
        float v = e2[j] * inv2;
        v += __shfl_xor_sync(0xffffffffu, v, 1);
        v += __shfl_xor_sync(0xffffffffu, v, 2);
        v += __shfl_xor_sync(0xffffffffu, v, 4);
        v += __shfl_xor_sync(0xffffffffu, v, 8);
        rs[j] = v;
    }
    float u = 0.f;
#pragma unroll
    for (int r = 0; r < 16; ++r) {
        float rw = __shfl_sync(0xffffffffu, rs[r >> 1], (r & 1) << 4);
        if (lane < 16) u = fmaf(rw, g_Ms[r * 16 + lane], u);
    }
    if (lane < 16) {
        g_U[(size_t)n * 16 + lane] = u;
        g_V[(size_t)n * 16 + lane] = cs;
    }
}

// ---------------- stage 3: tile-parallel P = exp2(U·V) -> fp16 + partial rowsums ----------------
__global__ void k_smax2() {
    int kt = blockIdx.x, qt = blockIdx.y, b = blockIdx.z;
    bool pad = (kt == qt + 1) && ((qt & 1) == 0);
    if (kt > qt && !pad) return;
    int tid = threadIdx.x;
    int row = tid >> 2, sub = tid & 3;
    int wid = tid >> 5, lane = tid & 31;
    __half* gp = g_Ph + ((size_t)b * SS + (size_t)qt * 64) * SS + (size_t)kt * 64;
    if (pad) {
        __half2 z = __floats2half2_rn(0.f, 0.f);
#pragma unroll
        for (int r = 0; r < 8; ++r)
            *(__half2*)(gp + (size_t)(wid * 8 + r) * SS + 2 * lane) = z;
        return;
    }
    __shared__ float Us[64 * 20];
    __shared__ float Vs[64 * 20];
    __shared__ float Ps[64 * 66];
    {
        int vr = tid >> 2, c4 = (tid & 3) * 4;
        *(float4*)(Us + vr * 20 + c4) =
            *(const float4*)(g_U + ((size_t)b * SS + (size_t)qt * 64 + vr) * 16 + c4);
        *(float4*)(Vs + vr * 20 + c4) =
            *(const float4*)(g_V + ((size_t)b * SS + (size_t)kt * 64 + vr) * 16 + c4);
    }
    __syncthreads();
    float ur[16];
#pragma unroll
    for (int i = 0; i < 16; ++i) ur[i] = Us[row * 20 + i];
    float psum = 0.f;
    bool diag = (kt == qt);
#pragma unroll
    for (int j = 0; j < 16; ++j) {
        int key = sub + 4 * j;
        const float* vv = Vs + key * 20;
        float s = 0.f;
#pragma unroll
        for (int i = 0; i < 16; ++i) s = fmaf(ur[i], vv[i], s);
        float p = (diag && key > row) ? 0.f : fexp2(s);
        Ps[row * 66 + key] = p;
        psum += p;
    }
    psum += __shfl_xor_sync(0xffffffffu, psum, 1);
    psum += __shfl_xor_sync(0xffffffffu, psum, 2);
    if (sub == 0)
        g_Part[((size_t)b * SS + (size_t)qt * 64 + row) * 64 + kt] = psum;
    __syncthreads();
#pragma unroll
    for (int r = 0; r < 8; ++r) {
        int rr = wid * 8 + r;
        float2 v2 = *(float2*)(Ps + rr * 66 + 2 * lane);
        *(__half2*)(gp + (size_t)rr * SS + 2 * lane) = __floats2half2_rn(v2.x, v2.y);
    }
}
__global__ void k_lr() {
    int row = blockIdx.x * 8 + (threadIdx.x >> 5);
    int lane = threadIdx.x & 31;
    int qt = (row & (SS - 1)) >> 6;
    const float* part = g_Part + (size_t)row * 64;
    float s = 0.f;
    if (lane <= qt) s = part[lane];
    if (lane + 32 <= qt) s += part[lane + 32];
#pragma unroll
    for (int o = 16; o; o >>= 1) s += __shfl_xor_sync(0xffffffffu, s, o);
    if (lane == 0) g_Lr[row] = 1.0f / s;
}

// ---------------- stage 3b: x -> fp16 (coalesced); W -> fp16 ----------------
__global__ void k_xh(const float* __restrict__ x) {
    size_t i = ((size_t)blockIdx.x * blockDim.x + threadIdx.x) * 8;
    float4 a = *(const float4*)(x + i);
    float4 b = *(const float4*)(x + i + 4);
    __half2 h[4];
    h[0] = __floats2half2_rn(a.x, a.y);
    h[1] = __floats2half2_rn(a.z, a.w);
    h[2] = __floats2half2_rn(b.x, b.y);
    h[3] = __floats2half2_rn(b.z, b.w);
    *(uint4*)(g_Xh + i) = *(uint4*)h;
}
__global__ void k_wh(const float* __restrict__ w) {
    int i = blockIdx.x * blockDim.x + threadIdx.x;
    g_Wh[i] = __float2half_rn(w[i]);
}

// ---------------- fp16 mma GEMM core: CTA 128x128, 2x4 warps (warp 64x32) ----------------
// 3-stage cp.async ring, k-chunk 64, ldmatrix fragment loads. (R15 mainloop — validated optimum)
__device__ __forceinline__ void load_tileA(uint32_t au, const __half* Ag, int ldA, int k0, int tid) {
#pragma unroll
    for (int i = 0; i < 4; ++i) {
        int idx = tid + i * 256;
        int row = idx >> 3, seg = idx & 7;
        cpa16(au + (row * APAD2 + seg * 8) * 2, Ag + (size_t)row * ldA + k0 + seg * 8);
    }
}
template <bool BT>
__device__ __forceinline__ void load_tileB(uint32_t bu, const __half* Bg, int ldB, int k0, int tid) {
    if (BT) {
#pragma unroll
        for (int i = 0; i < 4; ++i) {
            int idx = tid + i * 256;
            int row = idx >> 4, seg = idx & 15;
            cpa16(bu + (row * BPADT + seg * 8) * 2, Bg + (size_t)(k0 + row) * ldB + seg * 8);
        }
    } else {
#pragma unroll
        for (int i = 0; i < 4; ++i) {
            int idx = tid + i * 256;
            int row = idx >> 3, seg = idx & 7;
            cpa16(bu + (row * APAD2 + seg * 8) * 2, Bg + (size_t)row * ldB + k0 + seg * 8);
        }
    }
}

template <bool BT>
__device__ __forceinline__ void gemm_f16(float* smf,
                                         const __half* Ag, int ldA,
                                         const __half* Bg, int ldB,
                                         int nch, float acc[4][4][4], int tid) {
    __half* sm = (__half*)smf;
    int wid = tid >> 5, lane = tid & 31;
    int wm = wid & 1, wn = wid >> 1;
    uint32_t smu = s2u(sm);

    uint32_t a_off = ((wm * 64 + (lane & 7) + ((lane >> 3) & 1) * 8) * APAD2 + (lane >> 4) * 8) * 2;
    uint32_t b_off;
    if (BT) b_off = (((lane & 7) + ((lane >> 3) & 1) * 8) * BPADT + wn * 32 + (lane >> 4) * 8) * 2;
    else    b_off = ((wn * 32 + (lane & 7) + (lane >> 4) * 8) * APAD2 + ((lane >> 3) & 1) * 8) * 2;

#pragma unroll
    for (int s = 0; s < NSTAGE - 1; ++s) {
        uint32_t bu = smu + s * BUF2 * 2;
        load_tileA(bu, Ag, ldA, s * 64, tid);
        load_tileB<BT>(bu + ABUF2 * 2, Bg, ldB, s * 64, tid);
        CPA_COMMIT();
    }
    int stg = 0;
    for (int c = 0; c < nch; ++c) {
        asm volatile("cp.async.wait_group %0;" :: "n"(NSTAGE - 2) : "memory");
        __syncthreads();
        if (c + NSTAGE - 1 < nch) {
            int s = stg + NSTAGE - 1;
            if (s >= NSTAGE) s -= NSTAGE;
            uint32_t bu = smu + s * BUF2 * 2;
            load_tileA(bu, Ag, ldA, (c + NSTAGE - 1) * 64, tid);
            load_tileB<BT>(bu + ABUF2 * 2, Bg, ldB, (c + NSTAGE - 1) * 64, tid);
        }
        CPA_COMMIT();
        uint32_t bufu = smu + stg * BUF2 * 2;
        if (++stg == NSTAGE) stg = 0;
        uint32_t Au = bufu + a_off;
        uint32_t Bu = bufu + ABUF2 * 2 + b_off;
#pragma unroll
        for (int ks = 0; ks < 4; ++ks) {
            uint32_t a[4][4], bfr[4][2];
#pragma unroll
            for (int m2 = 0; m2 < 4; ++m2)
                LDSM4(a[m2][0], a[m2][1], a[m2][2], a[m2][3],
                      Au + (m2 * 16 * APAD2 + ks * 16) * 2);
#pragma unroll
            for (int nb = 0; nb < 2; ++nb) {
                if (BT)
                    LDSM4T(bfr[2 * nb][0], bfr[2 * nb][1], bfr[2 * nb + 1][0], bfr[2 * nb + 1][1],
                           Bu + (ks * 16 * BPADT + nb * 16) * 2);
                else
                    LDSM4(bfr[2 * nb][0], bfr[2 * nb][1], bfr[2 * nb + 1][0], bfr[2 * nb + 1][1],
                          Bu + (nb * 16 * APAD2 + ks * 16) * 2);
            }
#pragma unroll
            for (int m2 = 0; m2 < 4; ++m2)
#pragma unroll
                for (int n2 = 0; n2 < 4; ++n2)
                    mma_f16(acc[m2][n2], a[m2], bfr[n2]);
        }
    }
    __syncthreads();
}

// ---------------- stage 4: context GEMM + fused epilogue -> g_Hh ----------------
// grid (x = nt FASTEST for P L2 reuse, y = mt big-first, z = b)
__global__ void __launch_bounds__(256, 2) k_ctx_mma(const float* __restrict__ alphap) {
    extern __shared__ __align__(16) float sm[];
    int nt = blockIdx.x;
    int mt = (gridDim.y - 1) - blockIdx.y;
    int b = blockIdx.z;
    int tid = threadIdx.x;
    int wid = tid >> 5, lane = tid & 31;
    int g = lane >> 2, t = lane & 3;
    int wm = wid & 1, wn = wid >> 1;

    const __half* Ag = g_Ph + ((size_t)b * SS + (size_t)mt * 128) * SS;
    const __half* Bg = g_Xh + (size_t)b * SS * DD + nt * 128;
    int nch = (mt + 1) * 2;

    float acc[4][4][4];
#pragma unroll
    for (int i = 0; i < 4; ++i)
#pragma unroll
        for (int j = 0; j < 4; ++j)
#pragma unroll
            for (int k = 0; k < 4; ++k) acc[i][j][k] = 0.f;

    gemm_f16<true>(sm, Ag, SS, Bg, DD, nch, acc, tid);

    // epilogue staging
    float* Vq = sm;           // [128][16]
    float* lrs = sm + 2048;   // [128]
    float* c2 = sm + 2176;    // [16][128]
    for (int i = tid; i < 2048; i += 256)
        Vq[i] = g_V[((size_t)b * SS + (size_t)mt * 128) * 16 + i];
    if (tid < 128) lrs[tid] = g_Lr[(size_t)b * SS + mt * 128 + tid];
    for (int i = tid; i < 2048; i += 256) {
        int cc = i >> 7, d = i & 127;
        c2[i] = g_CB2[cc * DD + nt * 128 + d];
    }
    __syncthreads();

    float alpha = __ldg(alphap);
#pragma unroll
    for (int m2 = 0; m2 < 4; ++m2) {
#pragma unroll
        for (int rr = 0; rr < 2; ++rr) {
            int row = wm * 64 + m2 * 16 + g + rr * 8;
            float lr = lrs[row];
            const float* vr = Vq + row * 16;
            __half* hrow = g_Hh + ((size_t)b * SS + (size_t)mt * 128 + row) * DD + nt * 128;
#pragma unroll
            for (int n2 = 0; n2 < 4; ++n2) {
                int col = wn * 32 + n2 * 8 + 2 * t;
                float tr0 = 0.f, tr1 = 0.f;
#pragma unroll
                for (int cc = 0; cc < 16; ++cc) {
                    float vv = vr[cc];
                    tr0 = fmaf(vv, c2[cc * 128 + col], tr0);
                    tr1 = fmaf(vv, c2[cc * 128 + col + 1], tr1);
                }
                float z0 = fmaf(acc[m2][n2][rr * 2 + 0], lr, alpha * tr0);
                float z1 = fmaf(acc[m2][n2][rr * 2 + 1], lr, alpha * tr1);
                z0 = gelu_exact(z0);
                z1 = gelu_exact(z1);
                *(__half2*)(hrow + col) = __floats2half2_rn(z0, z1);
            }
        }
    }
}

// ---------------- stage 5: out = H @ W^T + b ----------------
// grid (x = nt FASTEST for H L2 reuse, y = mt)
__global__ void __launch_bounds__(256, 2) k_out_mma(const float* __restrict__ ob,
                                                    float* __restrict__ out) {
    extern __shared__ __align__(16) float sm[];
    int nt = blockIdx.x;
    int mt = blockIdx.y;
    int tid = threadIdx.x;
    int wid = tid >> 5, lane = tid & 31;
    int g = lane >> 2, t = lane & 3;
    int wm = wid & 1, wn = wid >> 1;

    const __half* Ag = g_Hh + (size_t)mt * 128 * DD;
    const __half* Bg = g_Wh + (size_t)nt * 128 * DD;

    float acc[4][4][4];
#pragma unroll
    for (int i = 0; i < 4; ++i)
#pragma unroll
        for (int j = 0; j < 4; ++j)
#pragma unroll
            for (int k = 0; k < 4; ++k) acc[i][j][k] = 0.f;

    gemm_f16<false>(sm, Ag, DD, Bg, DD, 16, acc, tid);

    float* bs = sm;
    if (tid < 32) *(float4*)(bs + tid * 4) = *(const float4*)(ob + nt * 128 + tid * 4);
    __syncthreads();

#pragma unroll
    for (int m2 = 0; m2 < 4; ++m2) {
#pragma unroll
        for (int rr = 0; rr < 2; ++rr) {
            int row = wm * 64 + m2 * 16 + g + rr * 8;
            float* orow = out + ((size_t)mt * 128 + row) * DD + nt * 128;
#pragma unroll
            for (int n2 = 0; n2 < 4; ++n2) {
                int col = wn * 32 + n2 * 8 + 2 * t;
                float z0 = acc[m2][n2][rr * 2 + 0] + bs[col];
                float z1 = acc[m2][n2][rr * 2 + 1] + bs[col + 1];
                *(float2*)(orow + col) = make_float2(z0, z1);
            }
        }
    }
}

// ---------------- launcher ----------------
extern "C" void kernel_launch(void* const* d_in, const int* in_sizes, int n_in,
                              void* d_out, int out_size) {
    const float* x    = (const float*)d_in[0];
    const int*   nidx = (const int*)d_in[1];
    const float* nw   = (const float*)d_in[2];
    const float* nrec = (const float*)d_in[3];
    const float* rb   = (const float*)d_in[4];
    const float* cb   = (const float*)d_in[5];
    const float* ow   = (const float*)d_in[6];
    const float* ob   = (const float*)d_in[7];
    const float* alp  = (const float*)d_in[8];
    float* out = (float*)d_out;

    cudaFuncSetAttribute(k_ctx_mma, cudaFuncAttributeMaxDynamicSharedMemorySize, GSMEM);
    cudaFuncSetAttribute(k_out_mma, cudaFuncAttributeMaxDynamicSharedMemorySize, GSMEM);

    k_rbs1<<<dim3(16, 8), 256>>>(rb);
    k_rbs2<<<16, 256>>>();
    k_cbs<<<512, 256>>>(cb);
    k_cb2<<<64, 256>>>(cb);
    k_M<<<dim3(16, 16), 32>>>();
    k_route<<<(BB * SS * 32) / 256, 256>>>(nidx, nw, nrec);
    k_smax2<<<dim3(64, 64, BB), 256>>>();
    k_lr<<<BB * SS / 8, 256>>>();
    k_xh<<<(BB * SS * DD) / (256 * 8), 256>>>(x);
    k_wh<<<DD * DD / 256, 256>>>(ow);
    k_ctx_mma<<<dim3(8, 32, BB), 256, GSMEM>>>(alp);
    k_out_mma<<<dim3(8, BB * SS / 128), 256, GSMEM>>>(ob, out);
}